// round 6
// baseline (speedup 1.0000x reference)
#include <cuda_runtime.h>
#include <math.h>

#define NB 128
#define NC 3
#define FS 8

// scratch (no allocations allowed)
__device__ float g_A[8 * 256];            // combined DCT-project+resize operator
__device__ float g_dct[NB * NC * 64];     // dct_in  [128,3,8,8]
__device__ float g_grad[NB * NC * 64];    // grad_in [128,3,8,8]

// ---------------------------------------------------------------------------
// Kernel 0: reference computes x' = D (mask25 ⊙ (D X D^T)) D^T  (forward DCT
// applied twice -- NOT the inverse), then bilinear 256->8 (= 0.5/0.5 average
// of rows/cols 32a+15,32a+16). Collapsed:
//   dct_in = A X A^T,
//   A[a,n] = sum_{h<25} B[a,h] * s_h * cos(pi*(2n+1)*h/512)
//   B[a,h] = 0.5*sqrt(2/256)*(cos(pi*(2h+1)*(32a+15)/512)
//                            +cos(pi*(2h+1)*(32a+16)/512))
// s_0 = sqrt(1/256), s_h = sqrt(2/256) otherwise. Args exact in fp32.
// ---------------------------------------------------------------------------
__global__ void build_A_kernel() {
    int a = blockIdx.x;     // 0..7
    int n = threadIdx.x;    // 0..255
    int r0 = 32 * a + 15, r1 = 32 * a + 16;
    const float srow = 0.08838834764831845f; // sqrt(2/256)
    float acc = 0.f;
    for (int h = 0; h < 25; h++) {
        float sh = (h == 0) ? 0.0625f : srow;  // sqrt(1/256)=1/16
        float f = 2.f * h + 1.f;
        float Bah = 0.5f * srow * (cospif(f * r0 * (1.f / 512.f)) +
                                   cospif(f * r1 * (1.f / 512.f)));
        acc += Bah * sh * cospif(((2.f * n + 1.f) * h) * (1.f / 512.f));
    }
    g_A[a * 256 + n] = acc;
}

// ---------------------------------------------------------------------------
// Kernel 1: per image (b,c): stream X once.
//  - accumulate T = A @ X   (thread t owns column t, 8 accumulators)
//  - stash the 32 rows needed for Sobel (rows 32j+14..17)
//  - epilogue: dct_in = T @ A^T  (8x8), grad_in = resized Sobel magnitude
// ---------------------------------------------------------------------------
__global__ __launch_bounds__(256) void dct_grad_kernel(const float* __restrict__ x) {
    __shared__ float sA[2048];        //  8x256
    __shared__ float sRows[32][256];  // grad rows
    __shared__ float sT[2048];        //  8x256

    int img = blockIdx.x;
    const float* __restrict__ X = x + (size_t)img * 65536;
    int t = threadIdx.x;

    for (int i = t; i < 2048; i += 256) sA[i] = g_A[i];
    __syncthreads();

    float acc[8];
#pragma unroll
    for (int i = 0; i < 8; i++) acc[i] = 0.f;

    for (int h = 0; h < 256; h += 4) {
        float v0 = X[(h + 0) * 256 + t];
        float v1 = X[(h + 1) * 256 + t];
        float v2 = X[(h + 2) * 256 + t];
        float v3 = X[(h + 3) * 256 + t];
        int m = h & 31, j = h >> 5;
        if (m == 12) { sRows[j * 4 + 0][t] = v2; sRows[j * 4 + 1][t] = v3; }
        else if (m == 16) { sRows[j * 4 + 2][t] = v0; sRows[j * 4 + 3][t] = v1; }
#pragma unroll
        for (int i = 0; i < 8; i++) {
            acc[i] += sA[i * 256 + h + 0] * v0;
            acc[i] += sA[i * 256 + h + 1] * v1;
            acc[i] += sA[i * 256 + h + 2] * v2;
            acc[i] += sA[i * 256 + h + 3] * v3;
        }
    }
#pragma unroll
    for (int i = 0; i < 8; i++) sT[i * 256 + t] = acc[i];
    __syncthreads();

    if (t < 64) {
        int j = t >> 3, k = t & 7;
        // dct_in[j,k] = sum_w T[j,w] * A[k,w]
        float s = 0.f;
        for (int w = 0; w < 256; w++) s += sT[j * 256 + w] * sA[k * 256 + w];
        g_dct[img * 64 + j * 8 + k] = s;

        // grad_in[j,k] = mean of Sobel magnitude at rows 32j+{15,16}, cols 32k+{15,16}
        float gsum = 0.f;
#pragma unroll
        for (int pr = 1; pr <= 2; pr++) {
#pragma unroll
            for (int pc = 0; pc < 2; pc++) {
                int c = 32 * k + 15 + pc;
                int rb = j * 4 + pr;
                float p00 = sRows[rb - 1][c - 1], p01 = sRows[rb - 1][c], p02 = sRows[rb - 1][c + 1];
                float p10 = sRows[rb][c - 1],                              p12 = sRows[rb][c + 1];
                float p20 = sRows[rb + 1][c - 1], p21 = sRows[rb + 1][c], p22 = sRows[rb + 1][c + 1];
                float gx = (p02 - p00) + 2.f * (p12 - p10) + (p22 - p20);
                float gy = (p20 + 2.f * p21 + p22) - (p00 + 2.f * p01 + p02);
                gsum += sqrtf(gx * gx + gy * gy);
            }
        }
        g_grad[img * 64 + j * 8 + k] = 0.25f * gsum;
    }
}

// ---------------------------------------------------------------------------
// Kernel 2: per batch b: conv3x3(3->64) + folded BN + ReLU on both 8x8 inputs,
// channel-mean fusion gate, weighted blend, classifier GEMV -> out[b,2].
// ---------------------------------------------------------------------------
__global__ __launch_bounds__(256) void head_kernel(
    const float* __restrict__ cwd, const float* __restrict__ cbd,
    const float* __restrict__ gnd, const float* __restrict__ btd,
    const float* __restrict__ cwg, const float* __restrict__ cbg,
    const float* __restrict__ gng, const float* __restrict__ btg,
    const float* __restrict__ fw,  const float* __restrict__ fb,
    const float* __restrict__ clw, const float* __restrict__ clb,
    float* __restrict__ out)
{
    __shared__ float sid[3][10][10];
    __shared__ float sig[3][10][10];
    __shared__ float red0[8], red1[8];
    __shared__ float s_w;

    int b = blockIdx.x;
    int t = threadIdx.x;

    for (int i = t; i < 300; i += 256) { (&sid[0][0][0])[i] = 0.f; (&sig[0][0][0])[i] = 0.f; }
    __syncthreads();
    for (int i = t; i < 192; i += 256) {
        int ic = i >> 6, pix = i & 63, r = pix >> 3, c = pix & 7;
        sid[ic][r + 1][c + 1] = g_dct[b * 192 + i];
        sig[ic][r + 1][c + 1] = g_grad[b * 192 + i];
    }
    __syncthreads();

    const float inv = rsqrtf(1.f + 1e-5f);
    float dvals[16], gvals[16];
    float pf = 0.f;
#pragma unroll
    for (int it = 0; it < 16; it++) {
        int idx = it * 256 + t;
        int oc = idx >> 6, pix = idx & 63, r = pix >> 3, c = pix & 7;
        float ad = 0.f, ag = 0.f;
#pragma unroll
        for (int ic = 0; ic < 3; ic++)
#pragma unroll
            for (int kh = 0; kh < 3; kh++)
#pragma unroll
                for (int kw = 0; kw < 3; kw++) {
                    int wi = ((oc * 3 + ic) * 3 + kh) * 3 + kw;
                    ad += sid[ic][r + kh][c + kw] * __ldg(&cwd[wi]);
                    ag += sig[ic][r + kh][c + kw] * __ldg(&cwg[wi]);
                }
        float scd = __ldg(&gnd[oc]) * inv;
        float ofd = __ldg(&cbd[oc]) * scd + __ldg(&btd[oc]);
        float scg = __ldg(&gng[oc]) * inv;
        float ofg = __ldg(&cbg[oc]) * scg + __ldg(&btg[oc]);
        ad = fmaxf(ad * scd + ofd, 0.f);
        ag = fmaxf(ag * scg + ofg, 0.f);
        dvals[it] = ad; gvals[it] = ag;
        pf += __ldg(&fw[oc]) * (ad + ag);
    }
    // fusion gate: sigmoid(mean-dot + bias)
    for (int o = 16; o > 0; o >>= 1) pf += __shfl_down_sync(0xffffffff, pf, o);
    if ((t & 31) == 0) red0[t >> 5] = pf;
    __syncthreads();
    if (t == 0) {
        float s = 0.f;
        for (int i = 0; i < 8; i++) s += red0[i];
        s = s * (1.f / 64.f) + fb[0];
        s_w = 1.f / (1.f + expf(-s));
    }
    __syncthreads();
    float w = s_w;

    float p0 = 0.f, p1 = 0.f;
#pragma unroll
    for (int it = 0; it < 16; it++) {
        int idx = it * 256 + t;
        float f = w * dvals[it] + (1.f - w) * gvals[it];
        p0 += __ldg(&clw[idx]) * f;
        p1 += __ldg(&clw[4096 + idx]) * f;
    }
    for (int o = 16; o > 0; o >>= 1) {
        p0 += __shfl_down_sync(0xffffffff, p0, o);
        p1 += __shfl_down_sync(0xffffffff, p1, o);
    }
    if ((t & 31) == 0) { red0[t >> 5] = p0; red1[t >> 5] = p1; }
    __syncthreads();
    if (t == 0) {
        float a = 0.f, c = 0.f;
        for (int i = 0; i < 8; i++) { a += red0[i]; c += red1[i]; }
        out[b * 2 + 0] = a + clb[0];
        out[b * 2 + 1] = c + clb[1];
    }
}

extern "C" void kernel_launch(void* const* d_in, const int* in_sizes, int n_in,
                              void* d_out, int out_size) {
    const float* x = (const float*)d_in[0];
    build_A_kernel<<<8, 256>>>();
    dct_grad_kernel<<<NB * NC, 256>>>(x);
    head_kernel<<<NB, 256>>>(
        (const float*)d_in[1], (const float*)d_in[2], (const float*)d_in[3], (const float*)d_in[4],
        (const float*)d_in[5], (const float*)d_in[6], (const float*)d_in[7], (const float*)d_in[8],
        (const float*)d_in[9], (const float*)d_in[10], (const float*)d_in[11], (const float*)d_in[12],
        (float*)d_out);
}

// round 9
// speedup vs baseline: 1.1759x; 1.1759x over previous
#include <cuda_runtime.h>
#include <math.h>
#include <cmath>

#define NB 128
#define NC 3
#define FS 8

// scratch (no allocations allowed)
__device__ float g_dct[NB * NC * 64];     // dct_in  [128,3,8,8]
__device__ float g_grad[NB * NC * 64];    // grad_in [128,3,8,8]

// Combined DCT-project + bilinear-resize operator, passed by value (8KB param).
// dct_in = A X A^T,  A[a,n] = sum_{h<25} B[a,h] * s_h * cos(pi*(2n+1)*h/512)
// B[a,h] = 0.5*sqrt(2/256)*(cos(pi*(2h+1)*(32a+15)/512)+cos(pi*(2h+1)*(32a+16)/512))
struct AParam { float A[8 * 256]; };

// ---------------------------------------------------------------------------
// Kernel 1: per image (b,c): stream X once.
//  - T = A @ X (thread t owns column t, 8 accumulators, 16-row unroll = MLP 16)
//  - stash the 32 rows needed for Sobel (rows 32j+14..17)
//  - epilogue: dct_in = T @ A^T (warp-parallel), grad_in = Sobel magnitude
// ---------------------------------------------------------------------------
__global__ __launch_bounds__(256) void dct_grad_kernel(const float* __restrict__ x,
                                                       const AParam P) {
    __shared__ float sA[2048];        //  8x256
    __shared__ float sRows[32][256];  // grad rows
    __shared__ float sT[2048];        //  8x256

    int img = blockIdx.x;
    const float* __restrict__ X = x + (size_t)img * 65536;
    int t = threadIdx.x;

    for (int i = t; i < 2048; i += 256) sA[i] = P.A[i];
    __syncthreads();

    const float4* __restrict__ sA4 = (const float4*)sA;

    float acc[8];
#pragma unroll
    for (int i = 0; i < 8; i++) acc[i] = 0.f;

    for (int h = 0; h < 256; h += 16) {
        float v[16];
#pragma unroll
        for (int u = 0; u < 16; u++) v[u] = X[(h + u) * 256 + t];
        int g = h >> 5;
        if ((h & 31) == 0) { sRows[g * 4 + 0][t] = v[14]; sRows[g * 4 + 1][t] = v[15]; }
        else               { sRows[g * 4 + 2][t] = v[0];  sRows[g * 4 + 3][t] = v[1];  }
#pragma unroll
        for (int i = 0; i < 8; i++) {
#pragma unroll
            for (int q = 0; q < 4; q++) {
                float4 a = sA4[i * 64 + (h >> 2) + q];
                acc[i] += a.x * v[q * 4 + 0];
                acc[i] += a.y * v[q * 4 + 1];
                acc[i] += a.z * v[q * 4 + 2];
                acc[i] += a.w * v[q * 4 + 3];
            }
        }
    }
#pragma unroll
    for (int i = 0; i < 8; i++) sT[i * 256 + t] = acc[i];
    __syncthreads();

    // Epilogue, all 8 warps: warp j; lane = q*8+k, q in 0..3 quarters of w-range.
    int j = t >> 5;
    int lane = t & 31;
    int k = lane & 7, q = lane >> 3;
    const float4* T4 = (const float4*)(sT + j * 256);
    const float4* A4 = (const float4*)(sA + k * 256);
    float s = 0.f;
#pragma unroll
    for (int m = 0; m < 16; m++) {
        float4 tv = T4[q * 16 + m];
        float4 av = A4[q * 16 + m];
        s += tv.x * av.x + tv.y * av.y + tv.z * av.z + tv.w * av.w;
    }
    s += __shfl_xor_sync(0xffffffffu, s, 8);
    s += __shfl_xor_sync(0xffffffffu, s, 16);
    if (lane < 8) {
        g_dct[img * 64 + j * 8 + lane] = s;

        // grad_in[j,k]: mean Sobel magnitude at rows 32j+{15,16}, cols 32k+{15,16}
        int kk = lane;
        float gsum = 0.f;
#pragma unroll
        for (int pr = 1; pr <= 2; pr++) {
#pragma unroll
            for (int pc = 0; pc < 2; pc++) {
                int c = 32 * kk + 15 + pc;
                int rb = j * 4 + pr;
                float p00 = sRows[rb - 1][c - 1], p01 = sRows[rb - 1][c], p02 = sRows[rb - 1][c + 1];
                float p10 = sRows[rb][c - 1],                              p12 = sRows[rb][c + 1];
                float p20 = sRows[rb + 1][c - 1], p21 = sRows[rb + 1][c], p22 = sRows[rb + 1][c + 1];
                float gx = (p02 - p00) + 2.f * (p12 - p10) + (p22 - p20);
                float gy = (p20 + 2.f * p21 + p22) - (p00 + 2.f * p01 + p02);
                gsum += sqrtf(gx * gx + gy * gy);
            }
        }
        g_grad[img * 64 + j * 8 + kk] = 0.25f * gsum;
    }
}

// ---------------------------------------------------------------------------
// Kernel 2: per batch b: conv3x3(3->64) + folded BN + ReLU on both 8x8 inputs,
// channel-mean fusion gate, weighted blend, classifier GEMV -> out[b,2].
// ---------------------------------------------------------------------------
__global__ __launch_bounds__(256) void head_kernel(
    const float* __restrict__ cwd, const float* __restrict__ cbd,
    const float* __restrict__ gnd, const float* __restrict__ btd,
    const float* __restrict__ cwg, const float* __restrict__ cbg,
    const float* __restrict__ gng, const float* __restrict__ btg,
    const float* __restrict__ fw,  const float* __restrict__ fb,
    const float* __restrict__ clw, const float* __restrict__ clb,
    float* __restrict__ out)
{
    __shared__ float sid[3][10][10];
    __shared__ float sig[3][10][10];
    __shared__ float red0[8], red1[8];
    __shared__ float s_w;

    int b = blockIdx.x;
    int t = threadIdx.x;

    for (int i = t; i < 300; i += 256) { (&sid[0][0][0])[i] = 0.f; (&sig[0][0][0])[i] = 0.f; }
    __syncthreads();
    for (int i = t; i < 192; i += 256) {
        int ic = i >> 6, pix = i & 63, r = pix >> 3, c = pix & 7;
        sid[ic][r + 1][c + 1] = g_dct[b * 192 + i];
        sig[ic][r + 1][c + 1] = g_grad[b * 192 + i];
    }
    __syncthreads();

    const float inv = rsqrtf(1.f + 1e-5f);
    float dvals[16], gvals[16];
    float pf = 0.f;
#pragma unroll
    for (int it = 0; it < 16; it++) {
        int idx = it * 256 + t;
        int oc = idx >> 6, pix = idx & 63, r = pix >> 3, c = pix & 7;
        float ad = 0.f, ag = 0.f;
#pragma unroll
        for (int ic = 0; ic < 3; ic++)
#pragma unroll
            for (int kh = 0; kh < 3; kh++)
#pragma unroll
                for (int kw = 0; kw < 3; kw++) {
                    int wi = ((oc * 3 + ic) * 3 + kh) * 3 + kw;
                    ad += sid[ic][r + kh][c + kw] * __ldg(&cwd[wi]);
                    ag += sig[ic][r + kh][c + kw] * __ldg(&cwg[wi]);
                }
        float scd = __ldg(&gnd[oc]) * inv;
        float ofd = __ldg(&cbd[oc]) * scd + __ldg(&btd[oc]);
        float scg = __ldg(&gng[oc]) * inv;
        float ofg = __ldg(&cbg[oc]) * scg + __ldg(&btg[oc]);
        ad = fmaxf(ad * scd + ofd, 0.f);
        ag = fmaxf(ag * scg + ofg, 0.f);
        dvals[it] = ad; gvals[it] = ag;
        pf += __ldg(&fw[oc]) * (ad + ag);
    }
    for (int o = 16; o > 0; o >>= 1) pf += __shfl_down_sync(0xffffffff, pf, o);
    if ((t & 31) == 0) red0[t >> 5] = pf;
    __syncthreads();
    if (t == 0) {
        float s = 0.f;
        for (int i = 0; i < 8; i++) s += red0[i];
        s = s * (1.f / 64.f) + fb[0];
        s_w = 1.f / (1.f + expf(-s));
    }
    __syncthreads();
    float w = s_w;

    float p0 = 0.f, p1 = 0.f;
#pragma unroll
    for (int it = 0; it < 16; it++) {
        int idx = it * 256 + t;
        float f = w * dvals[it] + (1.f - w) * gvals[it];
        p0 += __ldg(&clw[idx]) * f;
        p1 += __ldg(&clw[4096 + idx]) * f;
    }
    for (int o = 16; o > 0; o >>= 1) {
        p0 += __shfl_down_sync(0xffffffff, p0, o);
        p1 += __shfl_down_sync(0xffffffff, p1, o);
    }
    if ((t & 31) == 0) { red0[t >> 5] = p0; red1[t >> 5] = p1; }
    __syncthreads();
    if (t == 0) {
        float a = 0.f, c = 0.f;
        for (int i = 0; i < 8; i++) { a += red0[i]; c += red1[i]; }
        out[b * 2 + 0] = a + clb[0];
        out[b * 2 + 1] = c + clb[1];
    }
}

extern "C" void kernel_launch(void* const* d_in, const int* in_sizes, int n_in,
                              void* d_out, int out_size) {
    const float* x = (const float*)d_in[0];

    // Host-side A (double precision): deterministic, recomputed every call.
    static AParam P;
    const double PI = 3.14159265358979323846;
    const double srow = std::sqrt(2.0 / 256.0);
    for (int a = 0; a < 8; a++) {
        int r0 = 32 * a + 15, r1 = 32 * a + 16;
        for (int n = 0; n < 256; n++) {
            double acc = 0.0;
            for (int h = 0; h < 25; h++) {
                double sh = (h == 0) ? std::sqrt(1.0 / 256.0) : srow;
                double f = 2.0 * h + 1.0;
                double Bah = 0.5 * srow * (std::cos(PI * f * r0 / 512.0) +
                                           std::cos(PI * f * r1 / 512.0));
                acc += Bah * sh * std::cos(PI * (2.0 * n + 1.0) * h / 512.0);
            }
            P.A[a * 256 + n] = (float)acc;
        }
    }

    dct_grad_kernel<<<NB * NC, 256>>>(x, P);
    head_kernel<<<NB, 256>>>(
        (const float*)d_in[1], (const float*)d_in[2], (const float*)d_in[3], (const float*)d_in[4],
        (const float*)d_in[5], (const float*)d_in[6], (const float*)d_in[7], (const float*)d_in[8],
        (const float*)d_in[9], (const float*)d_in[10], (const float*)d_in[11], (const float*)d_in[12],
        (float*)d_out);
}